// round 1
// baseline (speedup 1.0000x reference)
#include <cuda_runtime.h>
#include <cuda_fp16.h>
#include <cstdint>

#define T_  512
#define B_  128
#define I_  512
#define H_  1024
#define NG  4096   // 4 * H
#define KZ  1536   // H + I

// ---------------- device scratch (static: no allocation allowed) -------------
__device__ __half g_xh[(size_t)T_ * B_ * I_];     //  64 MB  x in fp16
__device__ __half g_gx[(size_t)T_ * B_ * NG];     // 512 MB  precomputed x-part of gates (+bias), fp16
__device__ __half g_Wh[(size_t)NG * H_];          //   8 MB  recurrent weights fp16, n = g*H + j
__device__ __half g_Wx[(size_t)NG * I_];          //   4 MB  input weights fp16
__device__ __half g_h[2][B_ * H_];                // ping-pong hidden state (fp16)
__device__ float  g_c[B_ * H_];                   // cell state fp32

// ---------------- helpers ----------------------------------------------------
__device__ __forceinline__ float sigm(float x) {
    return 1.0f / (1.0f + __expf(-x));
}
__device__ __forceinline__ float tanh_fast(float x) {
    float e = __expf(-2.0f * fabsf(x));          // in (0,1], never overflows
    float r = (1.0f - e) / (1.0f + e);
    return copysignf(r, x);
}

__device__ __forceinline__ void mma16816(float* d, const uint32_t* a, const uint32_t* b) {
    asm volatile(
        "mma.sync.aligned.m16n8k16.row.col.f32.f16.f16.f32 "
        "{%0,%1,%2,%3}, {%4,%5,%6,%7}, {%8,%9}, {%0,%1,%2,%3};\n"
        : "+f"(d[0]), "+f"(d[1]), "+f"(d[2]), "+f"(d[3])
        : "r"(a[0]), "r"(a[1]), "r"(a[2]), "r"(a[3]),
          "r"(b[0]), "r"(b[1]));
}

// ---------------- prep kernels ------------------------------------------------
__global__ void k_prep_weights(const float* __restrict__ Wf, const float* __restrict__ Wi,
                               const float* __restrict__ Wc, const float* __restrict__ Wo,
                               const float* __restrict__ bf, const float* __restrict__ bi,
                               const float* __restrict__ bc, const float* __restrict__ bo) {
    size_t idx = (size_t)blockIdx.x * blockDim.x + threadIdx.x;
    const size_t total = (size_t)NG * KZ;
    if (idx < total) {
        int n = (int)(idx / KZ);
        int k = (int)(idx % KZ);
        int g = n >> 10, j = n & 1023;
        const float* W = (g == 0) ? Wf : (g == 1) ? Wi : (g == 2) ? Wc : Wo;
        float v = W[(size_t)j * KZ + k];
        if (k < H_) g_Wh[(size_t)n * H_ + k]        = __float2half(v);
        else        g_Wx[(size_t)n * I_ + (k - H_)] = __float2half(v);
    }
    if (idx < NG) {
        // bias handled in gx epilogue via a small fp32 table: store into g_gx later.
        // (nothing here; biases passed directly to k_gx)
    }
    if (idx < (size_t)B_ * H_) {
        g_h[0][idx] = __float2half(0.0f);
        g_c[idx] = 0.0f;
    }
}

__global__ void k_convert_x(const float* __restrict__ x) {
    size_t idx = (size_t)blockIdx.x * blockDim.x + threadIdx.x;
    if (idx < (size_t)T_ * B_ * I_) g_xh[idx] = __float2half(x[idx]);
}

// ---------------- kernel A: gx = x @ Wx^T + b  (M=65536, N=4096, K=512) -------
// BM=128, BN=128, BK=32, 256 threads, warp grid 4(M) x 2(N), warp tile 32x64.
__global__ __launch_bounds__(256) void k_gx(const float* __restrict__ bf, const float* __restrict__ bi,
                                            const float* __restrict__ bc, const float* __restrict__ bo) {
    __shared__ __half As[128][40];
    __shared__ __half Bs[128][40];

    const int m0 = blockIdx.y * 128;
    const int n0 = blockIdx.x * 128;
    const int tid  = threadIdx.x;
    const int w    = tid >> 5;
    const int lane = tid & 31;
    const int gid  = lane >> 2;
    const int t4   = lane & 3;
    const int wm   = w >> 1;     // 0..3
    const int wn   = w & 1;      // 0..1

    float acc[2][8][4];
#pragma unroll
    for (int mt = 0; mt < 2; mt++)
#pragma unroll
        for (int nt = 0; nt < 8; nt++)
#pragma unroll
            for (int e = 0; e < 4; e++) acc[mt][nt][e] = 0.0f;

    for (int kb = 0; kb < I_; kb += 32) {
#pragma unroll
        for (int i = 0; i < 2; i++) {
            int cid = tid + i * 256;          // 0..511
            int r = cid >> 2, ch = cid & 3;
            *(uint4*)&As[r][ch * 8] = *(const uint4*)&g_xh[(size_t)(m0 + r) * I_ + kb + ch * 8];
            *(uint4*)&Bs[r][ch * 8] = *(const uint4*)&g_Wx[(size_t)(n0 + r) * I_ + kb + ch * 8];
        }
        __syncthreads();

#pragma unroll
        for (int ks = 0; ks < 2; ks++) {
            const int ko = ks * 16;
            uint32_t a[2][4], b[8][2];
#pragma unroll
            for (int mt = 0; mt < 2; mt++) {
                int r = wm * 32 + mt * 16 + gid;
                a[mt][0] = *(const uint32_t*)&As[r][ko + t4 * 2];
                a[mt][1] = *(const uint32_t*)&As[r + 8][ko + t4 * 2];
                a[mt][2] = *(const uint32_t*)&As[r][ko + t4 * 2 + 8];
                a[mt][3] = *(const uint32_t*)&As[r + 8][ko + t4 * 2 + 8];
            }
#pragma unroll
            for (int nt = 0; nt < 8; nt++) {
                int c = wn * 64 + nt * 8 + gid;
                b[nt][0] = *(const uint32_t*)&Bs[c][ko + t4 * 2];
                b[nt][1] = *(const uint32_t*)&Bs[c][ko + t4 * 2 + 8];
            }
#pragma unroll
            for (int mt = 0; mt < 2; mt++)
#pragma unroll
                for (int nt = 0; nt < 8; nt++)
                    mma16816(acc[mt][nt], a[mt], b[nt]);
        }
        __syncthreads();
    }

    // epilogue: add bias, store fp16
#pragma unroll
    for (int nt = 0; nt < 8; nt++) {
        int n = n0 + wn * 64 + nt * 8 + t4 * 2;
        int g = n >> 10, j = n & 1023;
        const float* bias = (g == 0) ? bf : (g == 1) ? bi : (g == 2) ? bc : bo;
        float b0 = bias[j], b1 = bias[j + 1];
#pragma unroll
        for (int mt = 0; mt < 2; mt++) {
            int m = m0 + wm * 32 + mt * 16 + gid;
            __half2 v0 = __floats2half2_rn(acc[mt][nt][0] + b0, acc[mt][nt][1] + b1);
            __half2 v1 = __floats2half2_rn(acc[mt][nt][2] + b0, acc[mt][nt][3] + b1);
            *(__half2*)&g_gx[(size_t)m * NG + n]       = v0;
            *(__half2*)&g_gx[(size_t)(m + 8) * NG + n] = v1;
        }
    }
}

// ---------------- kernel B: one LSTM timestep ---------------------------------
// gates[b, g, j] = gx[t,b,g,j] + sum_k h[b,k] * Wh[g*H+j, k]
// 128 blocks, each owns 8 consecutive j-columns for all 4 gates; full B=128 rows.
__global__ __launch_bounds__(256) void k_step(int t, float* __restrict__ out) {
    __shared__ __half hs[128][72];
    __shared__ __half ws[4][8][72];

    const __half* __restrict__ hin = g_h[t & 1];
    __half* __restrict__ hout      = g_h[(t + 1) & 1];

    const int j0   = blockIdx.x * 8;
    const int tid  = threadIdx.x;
    const int w    = tid >> 5;
    const int lane = tid & 31;
    const int gid  = lane >> 2;
    const int t4   = lane & 3;

    float acc[4][4] = {};   // [gate][c-frag]

    for (int kb = 0; kb < H_; kb += 64) {
        // h tile: 128 rows x 64 halfs (1024 x 16B chunks, 4 per thread)
#pragma unroll
        for (int i = 0; i < 4; i++) {
            int cid = tid + i * 256;
            int r = cid >> 3, ch = cid & 7;
            *(uint4*)&hs[r][ch * 8] = *(const uint4*)&hin[(size_t)r * H_ + kb + ch * 8];
        }
        // W tile: 4 gates x 8 rows x 64 halfs (256 chunks, 1 per thread)
        {
            int g = tid >> 6, rem = tid & 63;
            int jl = rem >> 3, ch = rem & 7;
            *(uint4*)&ws[g][jl][ch * 8] =
                *(const uint4*)&g_Wh[(size_t)(g * H_ + j0 + jl) * H_ + kb + ch * 8];
        }
        __syncthreads();

#pragma unroll
        for (int ks = 0; ks < 4; ks++) {
            const int ko = ks * 16;
            uint32_t a[4];
            const int r = w * 16 + gid;
            a[0] = *(const uint32_t*)&hs[r][ko + t4 * 2];
            a[1] = *(const uint32_t*)&hs[r + 8][ko + t4 * 2];
            a[2] = *(const uint32_t*)&hs[r][ko + t4 * 2 + 8];
            a[3] = *(const uint32_t*)&hs[r + 8][ko + t4 * 2 + 8];
#pragma unroll
            for (int g = 0; g < 4; g++) {
                uint32_t b[2];
                b[0] = *(const uint32_t*)&ws[g][gid][ko + t4 * 2];
                b[1] = *(const uint32_t*)&ws[g][gid][ko + t4 * 2 + 8];
                mma16816(acc[g], a, b);
            }
        }
        __syncthreads();
    }

    // epilogue: activations + cell update + outputs
#pragma unroll
    for (int hlf = 0; hlf < 2; hlf++) {
        const int b = w * 16 + gid + hlf * 8;
#pragma unroll
        for (int cc = 0; cc < 2; cc++) {
            const int j  = j0 + t4 * 2 + cc;
            const int ai = hlf * 2 + cc;
            const size_t gxbase = ((size_t)t * B_ + b) * NG + j;
            float pf = acc[0][ai] + __half2float(g_gx[gxbase + 0 * H_]);
            float pi = acc[1][ai] + __half2float(g_gx[gxbase + 1 * H_]);
            float pc = acc[2][ai] + __half2float(g_gx[gxbase + 2 * H_]);
            float po = acc[3][ai] + __half2float(g_gx[gxbase + 3 * H_]);
            float f  = sigm(pf);
            float ii = sigm(pi);
            float ct = tanh_fast(pc);
            float o  = sigm(po);
            float cold = g_c[b * H_ + j];
            float cnew = f * cold + ii * ct;
            g_c[b * H_ + j] = cnew;
            float h = o * tanh_fast(cnew);
            out[((size_t)t * B_ + b) * H_ + j] = h;
            hout[b * H_ + j] = __float2half(h);
        }
    }
}

// ---------------- launch ------------------------------------------------------
extern "C" void kernel_launch(void* const* d_in, const int* in_sizes, int n_in,
                              void* d_out, int out_size) {
    const float* x  = (const float*)d_in[0];
    const float* Wf = (const float*)d_in[1];
    const float* bf = (const float*)d_in[2];
    const float* Wi = (const float*)d_in[3];
    const float* bi = (const float*)d_in[4];
    const float* Wc = (const float*)d_in[5];
    const float* bc = (const float*)d_in[6];
    const float* Wo = (const float*)d_in[7];
    const float* bo = (const float*)d_in[8];
    float* out = (float*)d_out;

    {
        size_t total = (size_t)NG * KZ;
        int blocks = (int)((total + 255) / 256);
        k_prep_weights<<<blocks, 256>>>(Wf, Wi, Wc, Wo, bf, bi, bc, bo);
    }
    {
        size_t total = (size_t)T_ * B_ * I_;
        int blocks = (int)((total + 255) / 256);
        k_convert_x<<<blocks, 256>>>(x);
    }
    k_gx<<<dim3(NG / 128, (T_ * B_) / 128), 256>>>(bf, bi, bc, bo);

    for (int t = 0; t < T_; t++)
        k_step<<<H_ / 8, 256>>>(t, out);
}

// round 3
// speedup vs baseline: 1.7610x; 1.7610x over previous
#include <cuda_runtime.h>
#include <cuda_fp16.h>
#include <cstdint>

#define T_  512
#define B_  128
#define I_  512
#define H_  1024
#define NG  4096   // 4 * H
#define KZ  1536   // H + I
#define GRID_STEP 128

// ---------------- device scratch (static: no allocation allowed) -------------
__device__ __half g_xh[(size_t)T_ * B_ * I_];     //  64 MB  x in fp16
__device__ __half g_gx[(size_t)T_ * B_ * NG];     // 512 MB  precomputed x-part of gates (+bias), fp16
__device__ __half g_Wh[(size_t)NG * H_];          //   8 MB  recurrent weights fp16, n = g*H + j
__device__ __half g_Wx[(size_t)NG * I_];          //   4 MB  input weights fp16
__device__ __half g_h[2][B_ * H_];                // ping-pong hidden state (fp16)
__device__ int    g_flag[T_];                     // per-step completion counters

// ---------------- helpers ----------------------------------------------------
__device__ __forceinline__ float sigm(float x) {
    return 1.0f / (1.0f + __expf(-x));
}
__device__ __forceinline__ float tanh_fast(float x) {
    float e = __expf(-2.0f * fabsf(x));
    float r = (1.0f - e) / (1.0f + e);
    return copysignf(r, x);
}
__device__ __forceinline__ void mma16816(float* d, const uint32_t* a, uint32_t b0, uint32_t b1) {
    asm volatile(
        "mma.sync.aligned.m16n8k16.row.col.f32.f16.f16.f32 "
        "{%0,%1,%2,%3}, {%4,%5,%6,%7}, {%8,%9}, {%0,%1,%2,%3};\n"
        : "+f"(d[0]), "+f"(d[1]), "+f"(d[2]), "+f"(d[3])
        : "r"(a[0]), "r"(a[1]), "r"(a[2]), "r"(a[3]),
          "r"(b0), "r"(b1));
}
__device__ __forceinline__ void cp_async16(uint32_t smem_addr, const void* gptr) {
    asm volatile("cp.async.cg.shared.global [%0], [%1], 16;\n" :: "r"(smem_addr), "l"(gptr));
}
__device__ __forceinline__ int ld_acquire_gpu(const int* p) {
    int v;
    asm volatile("ld.acquire.gpu.b32 %0, [%1];\n" : "=r"(v) : "l"(p) : "memory");
    return v;
}

// ---------------- prep kernels ------------------------------------------------
__global__ void k_prep_weights(const float* __restrict__ Wf, const float* __restrict__ Wi,
                               const float* __restrict__ Wc, const float* __restrict__ Wo) {
    size_t idx = (size_t)blockIdx.x * blockDim.x + threadIdx.x;
    const size_t total = (size_t)NG * KZ;
    if (idx < total) {
        int n = (int)(idx / KZ);
        int k = (int)(idx % KZ);
        int g = n >> 10, j = n & 1023;
        const float* W = (g == 0) ? Wf : (g == 1) ? Wi : (g == 2) ? Wc : Wo;
        float v = W[(size_t)j * KZ + k];
        if (k < H_) g_Wh[(size_t)n * H_ + k]        = __float2half(v);
        else        g_Wx[(size_t)n * I_ + (k - H_)] = __float2half(v);
    }
    if (idx < (size_t)B_ * H_) g_h[0][idx] = __float2half(0.0f);
    if (idx < T_) g_flag[idx] = 0;
}

__global__ void k_convert_x(const float* __restrict__ x) {
    size_t idx = (size_t)blockIdx.x * blockDim.x + threadIdx.x;
    if (idx < (size_t)T_ * B_ * I_) g_xh[idx] = __float2half(x[idx]);
}

// ---------------- kernel A: gx = x @ Wx^T + b  (M=65536, N=4096, K=512) -------
__global__ __launch_bounds__(256) void k_gx(const float* __restrict__ bf, const float* __restrict__ bi,
                                            const float* __restrict__ bc, const float* __restrict__ bo) {
    __shared__ __half As[128][40];
    __shared__ __half Bs[128][40];

    const int m0 = blockIdx.y * 128;
    const int n0 = blockIdx.x * 128;
    const int tid  = threadIdx.x;
    const int w    = tid >> 5;
    const int lane = tid & 31;
    const int gid  = lane >> 2;
    const int t4   = lane & 3;
    const int wm   = w >> 1;
    const int wn   = w & 1;

    float acc[2][8][4];
#pragma unroll
    for (int mt = 0; mt < 2; mt++)
#pragma unroll
        for (int nt = 0; nt < 8; nt++)
#pragma unroll
            for (int e = 0; e < 4; e++) acc[mt][nt][e] = 0.0f;

    for (int kb = 0; kb < I_; kb += 32) {
#pragma unroll
        for (int i = 0; i < 2; i++) {
            int cid = tid + i * 256;
            int r = cid >> 2, ch = cid & 3;
            *(uint4*)&As[r][ch * 8] = *(const uint4*)&g_xh[(size_t)(m0 + r) * I_ + kb + ch * 8];
            *(uint4*)&Bs[r][ch * 8] = *(const uint4*)&g_Wx[(size_t)(n0 + r) * I_ + kb + ch * 8];
        }
        __syncthreads();

#pragma unroll
        for (int ks = 0; ks < 2; ks++) {
            const int ko = ks * 16;
            uint32_t a[2][4], b[8][2];
#pragma unroll
            for (int mt = 0; mt < 2; mt++) {
                int r = wm * 32 + mt * 16 + gid;
                a[mt][0] = *(const uint32_t*)&As[r][ko + t4 * 2];
                a[mt][1] = *(const uint32_t*)&As[r + 8][ko + t4 * 2];
                a[mt][2] = *(const uint32_t*)&As[r][ko + t4 * 2 + 8];
                a[mt][3] = *(const uint32_t*)&As[r + 8][ko + t4 * 2 + 8];
            }
#pragma unroll
            for (int nt = 0; nt < 8; nt++) {
                int c = wn * 64 + nt * 8 + gid;
                b[nt][0] = *(const uint32_t*)&Bs[c][ko + t4 * 2];
                b[nt][1] = *(const uint32_t*)&Bs[c][ko + t4 * 2 + 8];
            }
#pragma unroll
            for (int mt = 0; mt < 2; mt++)
#pragma unroll
                for (int nt = 0; nt < 8; nt++)
                    mma16816(acc[mt][nt], a[mt], b[nt][0], b[nt][1]);
        }
        __syncthreads();
    }

#pragma unroll
    for (int nt = 0; nt < 8; nt++) {
        int n = n0 + wn * 64 + nt * 8 + t4 * 2;
        int g = n >> 10, j = n & 1023;
        const float* bias = (g == 0) ? bf : (g == 1) ? bi : (g == 2) ? bc : bo;
        float b0 = bias[j], b1 = bias[j + 1];
#pragma unroll
        for (int mt = 0; mt < 2; mt++) {
            int m = m0 + wm * 32 + mt * 16 + gid;
            __half2 v0 = __floats2half2_rn(acc[mt][nt][0] + b0, acc[mt][nt][1] + b1);
            __half2 v1 = __floats2half2_rn(acc[mt][nt][2] + b0, acc[mt][nt][3] + b1);
            *(__half2*)&g_gx[(size_t)m * NG + n]       = v0;
            *(__half2*)&g_gx[(size_t)(m + 8) * NG + n] = v1;
        }
    }
}

// ---------------- kernel B: persistent LSTM scan -------------------------------
// 128 blocks: block (mhalf, jb) owns rows [mhalf*64, +64) x cols j0=jb*16 (+16) x 4 gates.
// Wh slice (4 x 16 x 1024 fp16 = 128KB) resident in SMEM for all 512 steps.
// Per step: stream h (64 x 1024 fp16) via cp.async.cg (L2-coherent) in 8 double-
// buffered 16KB chunks; HMMA; fused gate epilogue; flag-based global sync.
#define WS_LD 1032          // 1024 + 8 halfs pad
#define HS_LD 136           // 128 + 8 halfs pad
#define SMEM_STEP_BYTES ((64 * WS_LD + 2 * 64 * HS_LD) * 2)

__global__ __launch_bounds__(256, 1) void k_scan(float* __restrict__ out) {
    extern __shared__ __half smem[];
    __half* ws = smem;                      // [64][WS_LD]  row = g*16 + jl
    __half* hs = smem + 64 * WS_LD;         // [2][64][HS_LD]

    const int tid  = threadIdx.x;
    const int w    = tid >> 5;
    const int lane = tid & 31;
    const int gid  = lane >> 2;
    const int t4   = lane & 3;
    const int wm   = w >> 1;                // 0..3  (m-tile)
    const int wn   = w & 1;                 // 0..1  (j-subrange)

    const int mhalf = blockIdx.x & 1;
    const int jb    = blockIdx.x >> 1;
    const int j0    = jb * 16;

    // ---- load Wh slice once: 64 rows x 1024 halfs = 8192 x 16B chunks ----
    for (int i = 0; i < 32; i++) {
        int cid = tid + i * 256;            // 0..8191 (16B chunks)
        int r = cid >> 7, ch = cid & 127;   // row 0..63, chunk 0..127
        int g = r >> 4, jl = r & 15;
        *(uint4*)&ws[r * WS_LD + ch * 8] =
            *(const uint4*)&g_Wh[(size_t)(g * H_ + j0 + jl) * H_ + ch * 8];
    }
    __syncthreads();

    const uint32_t hs_base = (uint32_t)__cvta_generic_to_shared(hs);

    // persistent per-thread cell state: rows (gid, gid+8), cols (t4*2, t4*2+1)
    float cst[4] = {0.f, 0.f, 0.f, 0.f};

    const int my_r   = wm * 16 + gid;                   // local row in 64-row half
    const int my_j   = j0 + wn * 8 + t4 * 2;            // global j (even)
    const int wrow   = wn * 8 + gid;                    // ws row within gate block

    for (int t = 0; t < T_; t++) {
        const __half* __restrict__ hin = g_h[t & 1];
        __half* __restrict__ hout      = g_h[(t + 1) & 1];

        if (t > 0) {
            if (tid == 0) {
                while (ld_acquire_gpu(&g_flag[t - 1]) != GRID_STEP) {}
            }
            __syncthreads();
        }

        const __half* hsrc = hin + (size_t)(mhalf * 64) * H_;

        // preload chunk 0
        {
#pragma unroll
            for (int i = 0; i < 4; i++) {
                int cid = tid + i * 256;        // 0..1023
                int r = cid >> 4, ch = cid & 15;
                cp_async16(hs_base + (uint32_t)((r * HS_LD + ch * 8) * 2),
                           hsrc + (size_t)r * H_ + ch * 8);
            }
            asm volatile("cp.async.commit_group;\n");
        }

        float acc[4][4];
#pragma unroll
        for (int g = 0; g < 4; g++)
#pragma unroll
            for (int e = 0; e < 4; e++) acc[g][e] = 0.f;

#pragma unroll 1
        for (int c8 = 0; c8 < 8; c8++) {
            if (c8 < 7) {
                int nb = (c8 + 1) & 1;
#pragma unroll
                for (int i = 0; i < 4; i++) {
                    int cid = tid + i * 256;
                    int r = cid >> 4, ch = cid & 15;
                    cp_async16(hs_base + (uint32_t)(((nb * 64 + r) * HS_LD + ch * 8) * 2),
                               hsrc + (size_t)r * H_ + (c8 + 1) * 128 + ch * 8);
                }
                asm volatile("cp.async.commit_group;\n");
                asm volatile("cp.async.wait_group 1;\n");
            } else {
                asm volatile("cp.async.wait_group 0;\n");
            }
            __syncthreads();

            const __half* hb = hs + (c8 & 1) * 64 * HS_LD;
#pragma unroll
            for (int ks = 0; ks < 8; ks++) {
                const int ko = ks * 16;
                uint32_t a[4];
                a[0] = *(const uint32_t*)&hb[(my_r)     * HS_LD + ko + t4 * 2];
                a[1] = *(const uint32_t*)&hb[(my_r + 8) * HS_LD + ko + t4 * 2];
                a[2] = *(const uint32_t*)&hb[(my_r)     * HS_LD + ko + t4 * 2 + 8];
                a[3] = *(const uint32_t*)&hb[(my_r + 8) * HS_LD + ko + t4 * 2 + 8];
                const int kb = c8 * 128 + ko;
#pragma unroll
                for (int g = 0; g < 4; g++) {
                    const __half* wr = &ws[(g * 16 + wrow) * WS_LD + kb];
                    uint32_t b0 = *(const uint32_t*)&wr[t4 * 2];
                    uint32_t b1 = *(const uint32_t*)&wr[t4 * 2 + 8];
                    mma16816(acc[g], a, b0, b1);
                }
            }
            __syncthreads();
        }

        // ---- epilogue: gates + cell update + writes ----
#pragma unroll
        for (int rr = 0; rr < 2; rr++) {
            const int b_row = mhalf * 64 + my_r + rr * 8;
            const size_t gxb = ((size_t)t * B_ + b_row) * NG + my_j;
            __half2 gf = *(const __half2*)&g_gx[gxb + 0 * H_];
            __half2 gi = *(const __half2*)&g_gx[gxb + 1 * H_];
            __half2 gc = *(const __half2*)&g_gx[gxb + 2 * H_];
            __half2 go = *(const __half2*)&g_gx[gxb + 3 * H_];
            float2 ff = __half22float2(gf);
            float2 fi = __half22float2(gi);
            float2 fc = __half22float2(gc);
            float2 fo = __half22float2(go);

            float hres[2];
#pragma unroll
            for (int cc = 0; cc < 2; cc++) {
                const int ai = rr * 2 + cc;
                float pf = acc[0][ai] + (cc ? ff.y : ff.x);
                float pi = acc[1][ai] + (cc ? fi.y : fi.x);
                float pc = acc[2][ai] + (cc ? fc.y : fc.x);
                float po = acc[3][ai] + (cc ? fo.y : fo.x);
                float f  = sigm(pf);
                float ii = sigm(pi);
                float ct = tanh_fast(pc);
                float o  = sigm(po);
                float cnew = f * cst[ai] + ii * ct;
                cst[ai] = cnew;
                hres[cc] = o * tanh_fast(cnew);
            }
            *(float2*)&out[((size_t)t * B_ + b_row) * H_ + my_j] = make_float2(hres[0], hres[1]);
            *(__half2*)&hout[(size_t)b_row * H_ + my_j] = __floats2half2_rn(hres[0], hres[1]);
        }

        __threadfence();
        __syncthreads();
        if (tid == 0) atomicAdd(&g_flag[t], 1);
    }
}

// ---------------- launch ------------------------------------------------------
extern "C" void kernel_launch(void* const* d_in, const int* in_sizes, int n_in,
                              void* d_out, int out_size) {
    const float* x  = (const float*)d_in[0];
    const float* Wf = (const float*)d_in[1];
    const float* bf = (const float*)d_in[2];
    const float* Wi = (const float*)d_in[3];
    const float* bi = (const float*)d_in[4];
    const float* Wc = (const float*)d_in[5];
    const float* bc = (const float*)d_in[6];
    const float* Wo = (const float*)d_in[7];
    const float* bo = (const float*)d_in[8];
    float* out = (float*)d_out;

    cudaFuncSetAttribute(k_scan, cudaFuncAttributeMaxDynamicSharedMemorySize, SMEM_STEP_BYTES);

    {
        size_t total = (size_t)NG * KZ;
        int blocks = (int)((total + 255) / 256);
        k_prep_weights<<<blocks, 256>>>(Wf, Wi, Wc, Wo);
    }
    {
        size_t total = (size_t)T_ * B_ * I_;
        int blocks = (int)((total + 255) / 256);
        k_convert_x<<<blocks, 256>>>(x);
    }
    k_gx<<<dim3(NG / 128, (T_ * B_) / 128), 256>>>(bf, bi, bc, bo);

    k_scan<<<GRID_STEP, 256, SMEM_STEP_BYTES>>>(out);
}